// round 6
// baseline (speedup 1.0000x reference)
#include <cuda_runtime.h>

// CG product: out[b] = concat_l concat_{(l1,l2)} einsum(CG[l1,l2,l], A_l1[b], B_l2[b])
// batch=4096, tau=16, LMAX=3. Output 4096 x 39936 fp32.

#define NROWS   156     // sum over l of (2l+1)*npairs(l) = 4 + 27 + 55 + 70
#define NTERMS  478     // total nonzero (row, m1) terms
#define OUT_PER_B 39936

// term k: x = a_row | (b_row<<8), y = coeff bits
__device__ int2 g_term[512];
__device__ int  g_rowinfo[NROWS];   // term_start | (nterms<<16)

// pair tables: packed l1*4+l2, in (l1 outer, l2 inner) enumeration order
__constant__ unsigned char c_pairs[34] = {
    // l=0 (4)
    0, 5, 10, 15,
    // l=1 (9)
    1, 4, 5, 6, 9, 10, 11, 14, 15,
    // l=2 (11)
    2, 5, 6, 7, 8, 9, 10, 11, 13, 14, 15,
    // l=3 (10)
    3, 6, 7, 9, 10, 11, 12, 13, 14, 15
};
__constant__ int c_pairBase[4] = {0, 4, 13, 24};
__constant__ int c_rowBase[4]  = {0, 4, 31, 86};   // cumulative rows per l
__constant__ int c_np[4]       = {4, 9, 11, 10};   // pairs per l

// ---------------------------------------------------------------------------
// Init: build row/term tables + CG coefficients. 1 block, 192 threads.
// Deterministic, replayed in the graph each call (~few us).
// ---------------------------------------------------------------------------
__global__ void cg_init_kernel() {
    __shared__ int s_nt[NROWS];
    __shared__ int s_start[NROWS];
    int t = threadIdx.x;

    int l = 0, l1 = 0, l2 = 0, Mv = 0, m1lo = 0, nt = 0;
    if (t < NROWS) {
        l = 3;
        if (t < 4) l = 0; else if (t < 31) l = 1; else if (t < 86) l = 2;
        int rr = t - c_rowBase[l];
        int np = c_np[l];
        int M  = rr / np;
        int pi = rr - M * np;
        int pc = c_pairs[c_pairBase[l] + pi];
        l1 = pc >> 2; l2 = pc & 3;
        Mv = M - l;
        m1lo = max(-l1, Mv - l2);
        int m1hi = min(l1, Mv + l2);
        nt = m1hi - m1lo + 1;
        s_nt[t] = nt;
    }
    __syncthreads();
    if (t == 0) {
        int run = 0;
        for (int i = 0; i < NROWS; ++i) { s_start[i] = run; run += s_nt[i]; }
    }
    __syncthreads();
    if (t < NROWS) {
        int start = s_start[t];
        g_rowinfo[t] = start | (nt << 16);

        double f[11];
        f[0] = 1.0;
        #pragma unroll
        for (int i = 1; i <= 10; ++i) f[i] = f[i - 1] * (double)i;

        for (int i = 0; i < nt; ++i) {
            int m1 = m1lo + i;
            int m2 = Mv - m1;
            int j1 = l1, j2 = l2, j = l, m = Mv;
            double pref = sqrt((2.0 * j + 1.0) * f[j + j1 - j2] * f[j - j1 + j2] *
                               f[j1 + j2 - j] / f[j1 + j2 + j + 1]);
            pref *= sqrt(f[j + m] * f[j - m] * f[j1 + m1] * f[j1 - m1] *
                         f[j2 + m2] * f[j2 - m2]);
            double s = 0.0;
            for (int k = 0; k <= j1 + j2 - j; ++k) {
                int d1 = j1 + j2 - j - k;
                int d2 = j1 - m1 - k;
                int d3 = j2 + m2 - k;
                int d4 = j - j2 + m1 + k;
                int d5 = j - j1 - m2 + k;
                if (d1 < 0 || d2 < 0 || d3 < 0 || d4 < 0 || d5 < 0) continue;
                double denom = f[k] * f[d1] * f[d2] * f[d3] * f[d4] * f[d5];
                s += ((k & 1) ? -1.0 : 1.0) / denom;
            }
            float cg = (float)(pref * s);
            int ar = l1 * l1 + m1 + l1;      // row in packed 16-row A block
            int br = l2 * l2 + m2 + l2;
            int2 tm;
            tm.x = ar | (br << 8);
            tm.y = __float_as_int(cg);
            g_term[start + i] = tm;
        }
    }
}

// ---------------------------------------------------------------------------
// Main: one block per batch element. Thread owns (p, 8 consecutive q);
// each warp (constant sub = t>>5) covers full rows. Writes 2x STG.128 per row.
// ---------------------------------------------------------------------------
__global__ void __launch_bounds__(256) cg_main_kernel(
    const float* __restrict__ A0, const float* __restrict__ A1,
    const float* __restrict__ A2, const float* __restrict__ A3,
    const float* __restrict__ B0, const float* __restrict__ B1,
    const float* __restrict__ B2, const float* __restrict__ B3,
    float* __restrict__ out)
{
    __shared__ __align__(16) float sA[256];   // 16 m-rows x 16 tau
    __shared__ __align__(16) float sB[256];
    __shared__ int2 s_term[NTERMS];
    __shared__ int  s_rows[NROWS];

    const int t = threadIdx.x;
    const int b = blockIdx.x;

    // load this batch element's irreps (A_l rows at offset l*l)
    {
        int r = t >> 4, c = t & 15;
        int l = (r >= 9) ? 3 : ((r >= 4) ? 2 : ((r >= 1) ? 1 : 0));
        int off = r - l * l;
        const float* As = (l == 0) ? A0 : ((l == 1) ? A1 : ((l == 2) ? A2 : A3));
        const float* Bs = (l == 0) ? B0 : ((l == 1) ? B1 : ((l == 2) ? B2 : B3));
        long base = ((long)b * (2 * l + 1) + off) * 16 + c;
        sA[t] = As[base];
        sB[t] = Bs[base];
    }
    for (int i = t; i < NTERMS; i += 256) s_term[i] = g_term[i];
    if (t < NROWS) s_rows[t] = g_rowinfo[t];
    __syncthreads();

    const int sub = t >> 5;            // 0..7, constant per warp
    const int p   = (t >> 1) & 15;
    const int q8  = (t & 1) << 3;
    float* ob = out + (long)b * OUT_PER_B + p * 16 + q8;
    const float* sAp = sA + p;
    const float* sBq = sB + q8;

    for (int r = sub; r < NROWS; r += 8) {
        int info = s_rows[r];
        int ts = info & 0xFFFF;
        int nt = info >> 16;
        float ax = 0.f, ay = 0.f, az = 0.f, aw = 0.f;
        float bx = 0.f, by = 0.f, bz = 0.f, bw = 0.f;
        for (int k = 0; k < nt; ++k) {
            int2 tm = s_term[ts + k];
            float ca = __int_as_float(tm.y) * sAp[(tm.x & 255) << 4];
            const float4* bp = (const float4*)(sBq + ((tm.x >> 8) << 4));
            float4 b0 = bp[0];
            float4 b1 = bp[1];
            ax = fmaf(ca, b0.x, ax); ay = fmaf(ca, b0.y, ay);
            az = fmaf(ca, b0.z, az); aw = fmaf(ca, b0.w, aw);
            bx = fmaf(ca, b1.x, bx); by = fmaf(ca, b1.y, by);
            bz = fmaf(ca, b1.z, bz); bw = fmaf(ca, b1.w, bw);
        }
        float4* o = (float4*)(ob + r * 256);
        o[0] = make_float4(ax, ay, az, aw);
        o[1] = make_float4(bx, by, bz, bw);
    }
}

extern "C" void kernel_launch(void* const* d_in, const int* in_sizes, int n_in,
                              void* d_out, int out_size) {
    // setup_inputs() builds the dict interleaved: A0,B0,A1,B1,A2,B2,A3,B3.
    // Detect ordering from sizes (A0 and B0 are both batch*16; A1 is batch*48).
    const float* A[4];
    const float* B[4];
    if (in_sizes[1] == in_sizes[0]) {
        // interleaved A0,B0,A1,B1,...
        for (int l = 0; l < 4; ++l) {
            A[l] = (const float*)d_in[2 * l];
            B[l] = (const float*)d_in[2 * l + 1];
        }
    } else {
        // A0..A3 then B0..B3
        for (int l = 0; l < 4; ++l) {
            A[l] = (const float*)d_in[l];
            B[l] = (const float*)d_in[4 + l];
        }
    }
    int nb = in_sizes[0] / 16;   // A0 is (batch, 1, 16)
    cg_init_kernel<<<1, 192>>>();
    cg_main_kernel<<<nb, 256>>>(A[0], A[1], A[2], A[3],
                                B[0], B[1], B[2], B[3],
                                (float*)d_out);
}

// round 10
// speedup vs baseline: 1.1544x; 1.1544x over previous
#include <cuda_runtime.h>

// CG product: out[b] = concat_l concat_{(l1,l2)} einsum(CG[l1,l2,l], A_l1[b], B_l2[b])
// batch=4096, tau=16, LMAX=3. Output 4096 x 39936 fp32. DRAM-write-bound.
// CG tables are built entirely at COMPILE TIME (constexpr) -> single kernel launch.

#define NROWS   156     // sum over l of (2l+1)*npairs(l) = 4 + 27 + 55 + 70
#define NTERMS  478     // total nonzero (row, m1) terms
#define OUT_PER_B 39936

struct alignas(8) Term {
    int   ab;   // (a_row*16) | ((b_row*16) << 16)  -- pre-scaled smem float offsets
    float c;    // CG coefficient
};

struct Tables {
    Term term[512];
    int  rowinfo[NROWS];   // term_start | (nterms << 16)
};

// ---- compile-time CG machinery ---------------------------------------------
constexpr double cfact(int n) {
    double r = 1.0;
    for (int i = 2; i <= n; ++i) r *= (double)i;
    return r;
}

constexpr double csqrt(double x) {
    if (x <= 0.0) return 0.0;
    double r = (x >= 1.0) ? x : 1.0;
    for (int i = 0; i < 64; ++i) {
        double nr = 0.5 * (r + x / r);
        if (nr == r) break;
        r = nr;
    }
    return r;
}

constexpr double cg_scalar(int j1, int m1, int j2, int m2, int j, int m) {
    if (m1 + m2 != m) return 0.0;
    double pref = csqrt((2.0 * j + 1.0) * cfact(j + j1 - j2) * cfact(j - j1 + j2) *
                        cfact(j1 + j2 - j) / cfact(j1 + j2 + j + 1));
    pref *= csqrt(cfact(j + m) * cfact(j - m) * cfact(j1 + m1) * cfact(j1 - m1) *
                  cfact(j2 + m2) * cfact(j2 - m2));
    double s = 0.0;
    for (int k = 0; k <= j1 + j2 - j; ++k) {
        int d1 = j1 + j2 - j - k;
        int d2 = j1 - m1 - k;
        int d3 = j2 + m2 - k;
        int d4 = j - j2 + m1 + k;
        int d5 = j - j1 - m2 + k;
        if (d1 < 0 || d2 < 0 || d3 < 0 || d4 < 0 || d5 < 0) continue;
        double denom = cfact(k) * cfact(d1) * cfact(d2) * cfact(d3) *
                       cfact(d4) * cfact(d5);
        s += ((k & 1) ? -1.0 : 1.0) / denom;
    }
    return pref * s;
}

constexpr Tables make_tables() {
    Tables T{};
    // allowed (l1,l2) pairs per output l, packed l1*4+l2, (l1 outer, l2 inner) order
    const unsigned char pairs[34] = {
        0, 5, 10, 15,                               // l=0 (4)
        1, 4, 5, 6, 9, 10, 11, 14, 15,              // l=1 (9)
        2, 5, 6, 7, 8, 9, 10, 11, 13, 14, 15,       // l=2 (11)
        3, 6, 7, 9, 10, 11, 12, 13, 14, 15          // l=3 (10)
    };
    const int pairBase[4] = {0, 4, 13, 24};
    const int npl[4]      = {4, 9, 11, 10};

    int run = 0, row = 0;
    for (int l = 0; l <= 3; ++l) {
        for (int Mi = 0; Mi < 2 * l + 1; ++Mi) {
            int Mv = Mi - l;
            for (int pi = 0; pi < npl[l]; ++pi) {
                int pc = pairs[pairBase[l] + pi];
                int l1 = pc >> 2, l2 = pc & 3;
                int m1lo = (-l1 > Mv - l2) ? -l1 : Mv - l2;
                int m1hi = ( l1 < Mv + l2) ?  l1 : Mv + l2;
                int start = run;
                for (int m1 = m1lo; m1 <= m1hi; ++m1) {
                    int m2 = Mv - m1;
                    int ar = l1 * l1 + m1 + l1;   // row in packed 16-row irrep block
                    int br = l2 * l2 + m2 + l2;
                    T.term[run].ab = (ar * 16) | ((br * 16) << 16);
                    T.term[run].c  = (float)cg_scalar(l1, m1, l2, m2, l, Mv);
                    ++run;
                }
                T.rowinfo[row] = start | ((m1hi - m1lo + 1) << 16);
                ++row;
            }
        }
    }
    return T;
}

__device__ const Tables g_tab = make_tables();

// ---------------------------------------------------------------------------
// Main: one block per batch element. Thread owns (p, 8 consecutive q);
// each warp (constant sub = t>>5) covers full 256-float rows.
// Per row: 2x STG.128 per thread -> one contiguous 1KB write per warp-row.
// ---------------------------------------------------------------------------
__global__ void __launch_bounds__(256) cg_main_kernel(
    const float* __restrict__ A0, const float* __restrict__ A1,
    const float* __restrict__ A2, const float* __restrict__ A3,
    const float* __restrict__ B0, const float* __restrict__ B1,
    const float* __restrict__ B2, const float* __restrict__ B3,
    float* __restrict__ out)
{
    __shared__ __align__(16) float sA[256];   // 16 m-rows x 16 tau
    __shared__ __align__(16) float sB[256];
    __shared__ Term s_term[NTERMS];
    __shared__ int  s_rows[NROWS];

    const int t = threadIdx.x;
    const int b = blockIdx.x;

    // load this batch element's irreps (irrep l packed at row offset l*l)
    {
        int r = t >> 4, c = t & 15;
        int l = (r >= 9) ? 3 : ((r >= 4) ? 2 : ((r >= 1) ? 1 : 0));
        int off = r - l * l;
        const float* As = (l == 0) ? A0 : ((l == 1) ? A1 : ((l == 2) ? A2 : A3));
        const float* Bs = (l == 0) ? B0 : ((l == 1) ? B1 : ((l == 2) ? B2 : B3));
        long base = ((long)b * (2 * l + 1) + off) * 16 + c;
        sA[t] = As[base];
        sB[t] = Bs[base];
    }
    for (int i = t; i < NTERMS; i += 256) s_term[i] = g_tab.term[i];
    if (t < NROWS) s_rows[t] = g_tab.rowinfo[t];
    __syncthreads();

    const int sub = t >> 5;            // 0..7, constant per warp
    const int p   = (t >> 1) & 15;
    const int q8  = (t & 1) << 3;
    float* ob = out + (long)b * OUT_PER_B + p * 16 + q8;
    const float* sAp = sA + p;
    const float* sBq = sB + q8;

    for (int r = sub; r < NROWS; r += 8) {
        int info = s_rows[r];
        int ts = info & 0xFFFF;
        int nt = info >> 16;
        float ax = 0.f, ay = 0.f, az = 0.f, aw = 0.f;
        float bx = 0.f, by = 0.f, bz = 0.f, bw = 0.f;
        for (int k = 0; k < nt; ++k) {
            Term tm = s_term[ts + k];
            float ca = tm.c * sAp[tm.ab & 0xFFFF];          // A broadcast (per-p)
            const float4* bp = (const float4*)(sBq + (tm.ab >> 16));  // 2-addr bcast
            float4 b0 = bp[0];
            float4 b1 = bp[1];
            ax = fmaf(ca, b0.x, ax); ay = fmaf(ca, b0.y, ay);
            az = fmaf(ca, b0.z, az); aw = fmaf(ca, b0.w, aw);
            bx = fmaf(ca, b1.x, bx); by = fmaf(ca, b1.y, by);
            bz = fmaf(ca, b1.z, bz); bw = fmaf(ca, b1.w, bw);
        }
        float4* o = (float4*)(ob + r * 256);
        __stcs(o,     make_float4(ax, ay, az, aw));   // write-once: evict-first
        __stcs(o + 1, make_float4(bx, by, bz, bw));
    }
}

extern "C" void kernel_launch(void* const* d_in, const int* in_sizes, int n_in,
                              void* d_out, int out_size) {
    // setup_inputs() builds the dict interleaved: A0,B0,A1,B1,A2,B2,A3,B3.
    // Detect ordering from sizes (A0 and B0 are both batch*16; A1 is batch*48).
    const float* A[4];
    const float* B[4];
    if (in_sizes[1] == in_sizes[0]) {
        for (int l = 0; l < 4; ++l) {               // interleaved
            A[l] = (const float*)d_in[2 * l];
            B[l] = (const float*)d_in[2 * l + 1];
        }
    } else {
        for (int l = 0; l < 4; ++l) {               // A0..A3 then B0..B3
            A[l] = (const float*)d_in[l];
            B[l] = (const float*)d_in[4 + l];
        }
    }
    int nb = in_sizes[0] / 16;   // A0 is (batch, 1, 16)
    cg_main_kernel<<<nb, 256>>>(A[0], A[1], A[2], A[3],
                                B[0], B[1], B[2], B[3],
                                (float*)d_out);
}